// round 8
// baseline (speedup 1.0000x reference)
#include <cuda_runtime.h>
#include <cuda_fp16.h>
#include <math.h>
#include <stdint.h>

#define NTOK 16384
#define DMODEL 1024
#define FF 4096
#define NEXP 8
#define CAP 2560
#define NA (NTOK*2)

// ---------------- device scratch (static, allocation-free) ----------------
__device__ __half g_buf[(size_t)NEXP*CAP*DMODEL];   //  42 MB dispatched activations (fp16)
__device__ __half g_h  [(size_t)NEXP*CAP*FF];       // 168 MB hidden activations (fp16)
__device__ float  g_y  [(size_t)NEXP*CAP*DMODEL];   //  84 MB expert outputs (fp32)
__device__ __half g_w1h[(size_t)NEXP*DMODEL*FF];    //  64 MB w1 fp16, transposed [E][FF][DMODEL]
__device__ __half g_w2h[(size_t)NEXP*FF*DMODEL];    //  64 MB w2 fp16, transposed [E][DMODEL][FF]
__device__ int   g_topi[NA];
__device__ float g_topv[NA];
__device__ int   g_apos[NA];
__device__ int   g_slot_a[NEXP*CAP];
__device__ int   g_kept[NEXP];

__device__ __forceinline__ void mma_f16(float* d, const uint32_t* a, const uint32_t* b) {
    asm volatile("mma.sync.aligned.m16n8k16.row.col.f32.f16.f16.f32 "
        "{%0,%1,%2,%3}, {%4,%5,%6,%7}, {%8,%9}, {%0,%1,%2,%3};"
        : "+f"(d[0]), "+f"(d[1]), "+f"(d[2]), "+f"(d[3])
        : "r"(a[0]), "r"(a[1]), "r"(a[2]), "r"(a[3]), "r"(b[0]), "r"(b[1]));
}
__device__ __forceinline__ void ldmx4(uint32_t& r0, uint32_t& r1, uint32_t& r2, uint32_t& r3,
                                      uint32_t addr) {
    asm volatile("ldmatrix.sync.aligned.m8n8.x4.shared.b16 {%0,%1,%2,%3}, [%4];"
        : "=r"(r0), "=r"(r1), "=r"(r2), "=r"(r3) : "r"(addr));
}
__device__ __forceinline__ uint32_t smem_u32(const void* p) {
    uint32_t a;
    asm("{ .reg .u64 t; cvta.to.shared.u64 t, %1; cvt.u32.u64 %0, t; }" : "=r"(a) : "l"(p));
    return a;
}
__device__ __forceinline__ void cp16(uint32_t dst, const void* src) {
    asm volatile("cp.async.cg.shared.global [%0], [%1], 16;" :: "r"(dst), "l"(src) : "memory");
}
#define CP_COMMIT() asm volatile("cp.async.commit_group;" ::: "memory")
#define CP_WAIT6()  asm volatile("cp.async.wait_group 6;" ::: "memory")

// ---------------- fp16 tensor-core grouped GEMM, 8-stage cp.async + ldmatrix --------
// C[z] = A[z](MxK rm fp16) @ B[z]^T (B stored [N][K] rm fp16) + bias[z].
// flags: bit0 = exact GELU, bit1 = fp16 output (else fp32).
// CTA tile 256(M)x128(N), k-chunk 32, 8 warps (4m x 2n), warp tile 64x64.
// Stage: A[256 rows][32 fp16] + B[128 rows][32 fp16]; rows = 64B = 4 x 16B chunks,
// chunk c stored at (c ^ ((row>>1)&3)); swizzle period-8 in rows -> conflict-free.
// 8 stages => 7 chunk-times of load slack (covers loaded L2/DRAM latency).
#define STAGE_BYTES 24576
#define NSTAGE 8

__global__ void __launch_bounds__(256, 1) moe_mma_kernel(
    const __half* __restrict__ Ab, const __half* __restrict__ Bb,
    const float* __restrict__ biasb, void* __restrict__ Cb,
    int N, int K, int flags,
    long sA, long sB, long sBias, long sC)
{
    extern __shared__ char smem[];
    const uint32_t sbase = smem_u32(smem);

    const __half* A = Ab + (size_t)blockIdx.z * sA;
    const __half* B = Bb + (size_t)blockIdx.z * sB;
    const float* bias = biasb + (size_t)blockIdx.z * sBias;

    const int tid = threadIdx.x;
    const int wid = tid >> 5, lane = tid & 31;
    const int wm = wid >> 1;
    const int wn = wid & 1;
    const int g = lane >> 2;
    const int t = lane & 3;
    const int bm = blockIdx.y * 256;
    const int bn = blockIdx.x * 128;

    const int s_row = tid >> 2;
    const int s_c   = tid & 3;
    const int s_cs  = s_c ^ ((s_row >> 1) & 3);

    const int lq = lane >> 3;
    const int lr = lane & 7;
    const int a_frow = wm * 64 + ((lq & 1) << 3) + lr;
    const int a_ks   = lq >> 1;
    const uint32_t a_sw = (a_frow >> 1) & 3;
    const int b_frow = wn * 64 + ((lq >> 1) << 3) + lr;
    const int b_ks   = lq & 1;
    const uint32_t b_sw = (b_frow >> 1) & 3;

    float acc[4][8][4];
#pragma unroll
    for (int mt = 0; mt < 4; mt++)
#pragma unroll
        for (int nt = 0; nt < 8; nt++)
#pragma unroll
            for (int q = 0; q < 4; q++) acc[mt][nt][q] = 0.f;

    const int nch = K >> 5;
    const __half* Agb = A + (size_t)(bm + s_row) * K + s_c * 8;
    const __half* Bgb = B + (size_t)(bn + s_row) * K + s_c * 8;

    // prologue: issue stages 0..6
#pragma unroll
    for (int s = 0; s < NSTAGE - 1; s++) {
        if (s < nch) {
            const int k0 = s << 5;
            uint32_t ab = sbase + s * STAGE_BYTES;
#pragma unroll
            for (int l = 0; l < 4; l++)
                cp16(ab + (uint32_t)(((s_row + l * 64) * 4 + s_cs) * 16), Agb + (size_t)l * 64 * K + k0);
            uint32_t bb = ab + 16384;
#pragma unroll
            for (int l = 0; l < 2; l++)
                cp16(bb + (uint32_t)(((s_row + l * 64) * 4 + s_cs) * 16), Bgb + (size_t)l * 64 * K + k0);
        }
        CP_COMMIT();
    }
    CP_WAIT6();
    __syncthreads();

    for (int i = 0; i < nch; i++) {
        const int slot = i & (NSTAGE - 1);
        if (i + NSTAGE - 1 < nch) {
            const int k0 = (i + NSTAGE - 1) << 5;
            uint32_t ab = sbase + ((i + NSTAGE - 1) & (NSTAGE - 1)) * STAGE_BYTES;
#pragma unroll
            for (int l = 0; l < 4; l++)
                cp16(ab + (uint32_t)(((s_row + l * 64) * 4 + s_cs) * 16), Agb + (size_t)l * 64 * K + k0);
            uint32_t bb = ab + 16384;
#pragma unroll
            for (int l = 0; l < 2; l++)
                cp16(bb + (uint32_t)(((s_row + l * 64) * 4 + s_cs) * 16), Bgb + (size_t)l * 64 * K + k0);
        }
        CP_COMMIT();

        const uint32_t abase = sbase + slot * STAGE_BYTES + a_frow * 64;
        const uint32_t bbase = sbase + slot * STAGE_BYTES + 16384 + b_frow * 64;
#pragma unroll
        for (int ks = 0; ks < 2; ks++) {
            const uint32_t a_off = (((uint32_t)(2 * ks + a_ks) ^ a_sw) << 4);
            const uint32_t b_off = (((uint32_t)(2 * ks + b_ks) ^ b_sw) << 4);
            uint32_t af[4][4], bf[8][2];
#pragma unroll
            for (int mt = 0; mt < 4; mt++)
                ldmx4(af[mt][0], af[mt][1], af[mt][2], af[mt][3],
                      abase + mt * 1024 + a_off);
#pragma unroll
            for (int ntp = 0; ntp < 4; ntp++)
                ldmx4(bf[2*ntp][0], bf[2*ntp][1], bf[2*ntp+1][0], bf[2*ntp+1][1],
                      bbase + ntp * 1024 + b_off);
#pragma unroll
            for (int mt = 0; mt < 4; mt++)
#pragma unroll
                for (int nt = 0; nt < 8; nt++)
                    mma_f16(acc[mt][nt], af[mt], bf[nt]);
        }
        CP_WAIT6();
        __syncthreads();
    }

    // ---- epilogue ----
    const int do_gelu = flags & 1, out_half = flags & 2;
#pragma unroll
    for (int mt = 0; mt < 4; mt++) {
        const int row = bm + wm * 64 + mt * 16 + g;
#pragma unroll
        for (int nt = 0; nt < 8; nt++) {
            const int col = bn + wn * 64 + nt * 8 + 2 * t;
            const float bz0 = bias[col], bz1 = bias[col + 1];
            float v[4] = { acc[mt][nt][0] + bz0, acc[mt][nt][1] + bz1,
                           acc[mt][nt][2] + bz0, acc[mt][nt][3] + bz1 };
            if (do_gelu) {
#pragma unroll
                for (int q = 0; q < 4; q++)
                    v[q] = 0.5f * v[q] * (1.0f + erff(v[q] * 0.70710678118654752f));
            }
            if (out_half) {
                __half* C = (__half*)Cb + (size_t)blockIdx.z * sC;
                *(__half2*)(C + (size_t)row * N + col)       = __floats2half2_rn(v[0], v[1]);
                *(__half2*)(C + (size_t)(row + 8) * N + col) = __floats2half2_rn(v[2], v[3]);
            } else {
                float* C = (float*)Cb + (size_t)blockIdx.z * sC;
                *(float2*)(C + (size_t)row * N + col)       = make_float2(v[0], v[1]);
                *(float2*)(C + (size_t)(row + 8) * N + col) = make_float2(v[2], v[3]);
            }
        }
    }
}

// ---------------- weight convert + transpose: [E][K][N] fp32 -> [E][N][K] fp16 -------
// 64(k) x 32(n) tiles; fp32 loads 128B-coalesced, fp16 stores 128B-coalesced half2.
__global__ void __launch_bounds__(256) convert_w_kernel(const float* __restrict__ in,
                                                        __half* __restrict__ out,
                                                        int K, int N) {
    __shared__ float tile[32][65];
    const float* w = in + (size_t)blockIdx.z * K * N;
    __half* o = out + (size_t)blockIdx.z * N * K;
    int n0 = blockIdx.x * 32, k0 = blockIdx.y * 64;
    int tx = threadIdx.x & 31, ty = threadIdx.x >> 5;   // 32 x 8
#pragma unroll
    for (int i = 0; i < 8; i++) {
        int k = ty + i * 8;
        tile[tx][k] = w[(size_t)(k0 + k) * N + n0 + tx];
    }
    __syncthreads();
#pragma unroll
    for (int i = 0; i < 4; i++) {
        int n = ty * 4 + i;
        __half2 h = __floats2half2_rn(tile[n][2 * tx], tile[n][2 * tx + 1]);
        *(__half2*)(o + (size_t)(n0 + n) * K + k0 + 2 * tx) = h;
    }
}

// ---------------- router: logits -> softmax -> top2 ----------------
__global__ void __launch_bounds__(256) router_kernel(const float* __restrict__ x,
                                                     const float* __restrict__ wr,
                                                     const float* __restrict__ br) {
    __shared__ float swT[NEXP][DMODEL];
    int tid = threadIdx.x;
    for (int i = tid; i < DMODEL * NEXP; i += 256) {
        int d = i >> 3, e = i & 7;
        swT[e][d] = wr[i];
    }
    __syncthreads();
    int warp = tid >> 5, lane = tid & 31;
    int token = blockIdx.x * 8 + warp;
    const float* xr = x + (size_t)token * DMODEL;
    float p[NEXP];
#pragma unroll
    for (int e = 0; e < NEXP; e++) p[e] = 0.f;
    for (int j = lane; j < DMODEL; j += 32) {
        float xv = xr[j];
#pragma unroll
        for (int e = 0; e < NEXP; e++) p[e] = fmaf(xv, swT[e][j], p[e]);
    }
#pragma unroll
    for (int e = 0; e < NEXP; e++) {
#pragma unroll
        for (int off = 16; off; off >>= 1)
            p[e] += __shfl_xor_sync(0xffffffffu, p[e], off);
    }
    if (lane == 0) {
        float mx = -1e30f;
#pragma unroll
        for (int e = 0; e < NEXP; e++) { p[e] += br[e]; mx = fmaxf(mx, p[e]); }
        float s = 0.f;
#pragma unroll
        for (int e = 0; e < NEXP; e++) { p[e] = expf(p[e] - mx); s += p[e]; }
        float inv = 1.f / s;
#pragma unroll
        for (int e = 0; e < NEXP; e++) p[e] *= inv;
        int b0 = 0; float v0 = p[0];
#pragma unroll
        for (int e = 1; e < NEXP; e++) if (p[e] > v0) { v0 = p[e]; b0 = e; }
        int b1 = -1; float v1 = -1.f;
#pragma unroll
        for (int e = 0; e < NEXP; e++) if (e != b0 && p[e] > v1) { v1 = p[e]; b1 = e; }
        g_topi[token*2]   = b0;  g_topv[token*2]   = v0;
        g_topi[token*2+1] = b1;  g_topv[token*2+1] = v1;
    }
}

// ---------------- arrival-order capacity scan (conflict-free, register-packed) -------
__global__ void __launch_bounds__(1024) scan_kernel() {
    __shared__ int scnt[NEXP][1024];
    const int tid = threadIdx.x, wid = tid >> 5, lane = tid & 31;

    int4 vv[8];
#pragma unroll
    for (int q = 0; q < 8; q++) vv[q] = ((const int4*)g_topi)[tid * 8 + q];

    uint64_t hc = 0;
#pragma unroll
    for (int q = 0; q < 8; q++) {
        hc += 1ULL << (vv[q].x * 8);
        hc += 1ULL << (vv[q].y * 8);
        hc += 1ULL << (vv[q].z * 8);
        hc += 1ULL << (vv[q].w * 8);
    }
#pragma unroll
    for (int e = 0; e < NEXP; e++)
        scnt[e][tid] = (int)((hc >> (e * 8)) & 0xff);
    __syncthreads();

    if (wid < NEXP) {
        const int e = wid;
        int run = 0;
#pragma unroll 4
        for (int r = 0; r < 32; r++) {
            int v = scnt[e][r * 32 + lane];
            int x = v;
#pragma unroll
            for (int off = 1; off < 32; off <<= 1) {
                int y = __shfl_up_sync(0xffffffffu, x, off);
                if (lane >= off) x += y;
            }
            scnt[e][r * 32 + lane] = run + x - v;
            run += __shfl_sync(0xffffffffu, x, 31);
        }
        if (lane == 0) g_kept[e] = run < CAP ? run : CAP;
    }
    __syncthreads();

    uint64_t b0 = 0, b1 = 0;
#pragma unroll
    for (int e = 0; e < 4; e++) b0 |= (uint64_t)(uint32_t)scnt[e][tid] << (e * 16);
#pragma unroll
    for (int e = 4; e < 8; e++) b1 |= (uint64_t)(uint32_t)scnt[e][tid] << ((e - 4) * 16);

    const int a0 = tid * 32;
#pragma unroll
    for (int q = 0; q < 8; q++) {
        int ids[4] = { vv[q].x, vv[q].y, vv[q].z, vv[q].w };
#pragma unroll
        for (int j = 0; j < 4; j++) {
            const int e = ids[j];
            const int a = a0 + q * 4 + j;
            const int sh = (e & 3) * 16;
            uint64_t w = (e < 4) ? b0 : b1;
            const int pos = (int)((w >> sh) & 0xffff);
            w += 1ULL << sh;
            if (e < 4) b0 = w; else b1 = w;
            if (pos < CAP) { g_apos[a] = pos; g_slot_a[e * CAP + pos] = a; }
            else           { g_apos[a] = -1; }
        }
    }
}

// ---------------- dispatch gather (fp32 -> fp16 activations) ----------------
__global__ void __launch_bounds__(256) dispatch_kernel(const float* __restrict__ x) {
    int r = blockIdx.x;
    int e = r / CAP, pos = r - e * CAP;
    uint2* dst = (uint2*)(g_buf + (size_t)r * DMODEL);
    if (pos < g_kept[e]) {
        int a = g_slot_a[r];
        float4 v = ((const float4*)(x + (size_t)(a >> 1) * DMODEL))[threadIdx.x];
        __half2 h0 = __floats2half2_rn(v.x, v.y);
        __half2 h1 = __floats2half2_rn(v.z, v.w);
        uint2 u;
        u.x = *reinterpret_cast<uint32_t*>(&h0);
        u.y = *reinterpret_cast<uint32_t*>(&h1);
        dst[threadIdx.x] = u;
    } else {
        dst[threadIdx.x] = make_uint2(0u, 0u);
    }
}

// ---------------- combine ----------------
__global__ void __launch_bounds__(256) combine_kernel(float* __restrict__ out) {
    int token = blockIdx.x;
    int a0 = token * 2;
    int p0 = g_apos[a0], p1 = g_apos[a0 + 1];
    float w0 = (p0 >= 0) ? g_topv[a0]     : 0.f;
    float w1 = (p1 >= 0) ? g_topv[a0 + 1] : 0.f;
    float ws = w0 + w1;
    int t4 = threadIdx.x;
    float4 acc = make_float4(0.f, 0.f, 0.f, 0.f);
    if (p0 >= 0) {
        const float4* r = (const float4*)(g_y + ((size_t)g_topi[a0] * CAP + p0) * DMODEL);
        float4 v = r[t4];
        acc.x = fmaf(w0, v.x, acc.x); acc.y = fmaf(w0, v.y, acc.y);
        acc.z = fmaf(w0, v.z, acc.z); acc.w = fmaf(w0, v.w, acc.w);
    }
    if (p1 >= 0) {
        const float4* r = (const float4*)(g_y + ((size_t)g_topi[a0 + 1] * CAP + p1) * DMODEL);
        float4 v = r[t4];
        acc.x = fmaf(w1, v.x, acc.x); acc.y = fmaf(w1, v.y, acc.y);
        acc.z = fmaf(w1, v.z, acc.z); acc.w = fmaf(w1, v.w, acc.w);
    }
    if (ws > 0.f) {
        float inv = 1.f / fmaxf(ws, 1e-6f);
        acc.x *= inv; acc.y *= inv; acc.z *= inv; acc.w *= inv;
    }
    ((float4*)(out + (size_t)token * DMODEL))[t4] = acc;
}

// ---------------- launch ----------------
#define SMEM_TOTAL (NSTAGE * STAGE_BYTES)   // 192 KB

extern "C" void kernel_launch(void* const* d_in, const int* in_sizes, int n_in,
                              void* d_out, int out_size) {
    const float* x  = (const float*)d_in[0];
    const float* wr = (const float*)d_in[1];
    const float* br = (const float*)d_in[2];
    const float* w1 = (const float*)d_in[3];
    const float* b1 = (const float*)d_in[4];
    const float* w2 = (const float*)d_in[5];
    const float* b2 = (const float*)d_in[6];
    float* y = (float*)d_out;

    __half *buf, *h, *w1h, *w2h;
    float *yy;
    cudaGetSymbolAddress((void**)&buf, g_buf);
    cudaGetSymbolAddress((void**)&h,   g_h);
    cudaGetSymbolAddress((void**)&yy,  g_y);
    cudaGetSymbolAddress((void**)&w1h, g_w1h);
    cudaGetSymbolAddress((void**)&w2h, g_w2h);

    cudaFuncSetAttribute(moe_mma_kernel, cudaFuncAttributeMaxDynamicSharedMemorySize, SMEM_TOTAL);

    // weights: fp32 [K][N] -> fp16 [N][K]
    convert_w_kernel<<<dim3(FF / 32, DMODEL / 64, NEXP), 256>>>(w1, w1h, DMODEL, FF);
    convert_w_kernel<<<dim3(DMODEL / 32, FF / 64, NEXP), 256>>>(w2, w2h, FF, DMODEL);

    router_kernel<<<NTOK / 8, 256>>>(x, wr, br);
    scan_kernel<<<1, 1024>>>();
    dispatch_kernel<<<NEXP * CAP, 256>>>(x);

    // GEMM1: h = fp16(GELU(buf @ w1 + b1))   [per expert: 2560x1024 @ 1024x4096]
    dim3 g1(FF / 128, CAP / 256, NEXP);       // 32 x 10 x 8
    moe_mma_kernel<<<g1, 256, SMEM_TOTAL>>>(buf, w1h, b1, (void*)h, FF, DMODEL, 3,
                              (long)CAP * DMODEL, (long)DMODEL * FF, FF, (long)CAP * FF);

    // GEMM2: y_e = h @ w2 + b2 (fp32 out)    [per expert: 2560x4096 @ 4096x1024]
    dim3 g2(DMODEL / 128, CAP / 256, NEXP);   // 8 x 10 x 8
    moe_mma_kernel<<<g2, 256, SMEM_TOTAL>>>(h, w2h, b2, (void*)yy, DMODEL, FF, 0,
                              (long)CAP * FF, (long)FF * DMODEL, DMODEL, (long)CAP * DMODEL);

    combine_kernel<<<NTOK, 256>>>(y);
}

// round 9
// speedup vs baseline: 1.1850x; 1.1850x over previous
#include <cuda_runtime.h>
#include <cuda_fp16.h>
#include <math.h>
#include <stdint.h>

#define NTOK 16384
#define DMODEL 1024
#define FF 4096
#define NEXP 8
#define CAP 2560
#define NA (NTOK*2)

// ---------------- device scratch (static, allocation-free) ----------------
__device__ __half g_buf[(size_t)NEXP*CAP*DMODEL];   //  42 MB dispatched activations (fp16)
__device__ __half g_h  [(size_t)NEXP*CAP*FF];       // 168 MB hidden activations (fp16)
__device__ float  g_y  [(size_t)NEXP*CAP*DMODEL];   //  84 MB expert outputs (fp32)
__device__ __half g_w1h[(size_t)NEXP*DMODEL*FF];    //  64 MB w1 fp16, transposed [E][FF][DMODEL]
__device__ __half g_w2h[(size_t)NEXP*FF*DMODEL];    //  64 MB w2 fp16, transposed [E][DMODEL][FF]
__device__ int   g_topi[NA];
__device__ float g_topv[NA];
__device__ int   g_apos[NA];
__device__ int   g_slot_a[NEXP*CAP];
__device__ int   g_kept[NEXP];

__device__ __forceinline__ void mma_f16(float* d, const uint32_t* a, const uint32_t* b) {
    asm volatile("mma.sync.aligned.m16n8k16.row.col.f32.f16.f16.f32 "
        "{%0,%1,%2,%3}, {%4,%5,%6,%7}, {%8,%9}, {%0,%1,%2,%3};"
        : "+f"(d[0]), "+f"(d[1]), "+f"(d[2]), "+f"(d[3])
        : "r"(a[0]), "r"(a[1]), "r"(a[2]), "r"(a[3]), "r"(b[0]), "r"(b[1]));
}
__device__ __forceinline__ void ldmx4(uint32_t& r0, uint32_t& r1, uint32_t& r2, uint32_t& r3,
                                      uint32_t addr) {
    asm volatile("ldmatrix.sync.aligned.m8n8.x4.shared.b16 {%0,%1,%2,%3}, [%4];"
        : "=r"(r0), "=r"(r1), "=r"(r2), "=r"(r3) : "r"(addr));
}
__device__ __forceinline__ uint32_t smem_u32(const void* p) {
    uint32_t a;
    asm("{ .reg .u64 t; cvta.to.shared.u64 t, %1; cvt.u32.u64 %0, t; }" : "=r"(a) : "l"(p));
    return a;
}
__device__ __forceinline__ void cp16(uint32_t dst, const void* src) {
    asm volatile("cp.async.cg.shared.global [%0], [%1], 16;" :: "r"(dst), "l"(src) : "memory");
}
#define CP_COMMIT() asm volatile("cp.async.commit_group;" ::: "memory")
#define CP_WAIT2()  asm volatile("cp.async.wait_group 2;" ::: "memory")

// ---------------- fp16 tensor-core grouped GEMM, 4-stage cp.async + ldmatrix --------
// C[z] = A[z](MxK rm fp16) @ B[z]^T (B stored [N][K] rm fp16) + bias[z].
// flags: bit0 = exact GELU, bit1 = fp16 output (else fp32).
// CTA tile 128(M)x128(N), k-chunk 32, 8 warps (2m x 4n), warp tile 64x32.
// 2 CTAs/SM (regs<=128, smem 64KB) so barrier stalls overlap across CTAs.
// Stage: A[128 rows][32 fp16] (8KB) + B[128 rows][32 fp16] (8KB); rows = 64B = 4 x 16B
// chunks, chunk c stored at (c ^ ((row>>1)&3)); period-8 in rows -> conflict-free.
#define STAGE_BYTES 16384
#define NSTAGE 4

__global__ void __launch_bounds__(256, 2) moe_mma_kernel(
    const __half* __restrict__ Ab, const __half* __restrict__ Bb,
    const float* __restrict__ biasb, void* __restrict__ Cb,
    int N, int K, int flags,
    long sA, long sB, long sBias, long sC)
{
    extern __shared__ char smem[];
    const uint32_t sbase = smem_u32(smem);

    const __half* A = Ab + (size_t)blockIdx.z * sA;
    const __half* B = Bb + (size_t)blockIdx.z * sB;
    const float* bias = biasb + (size_t)blockIdx.z * sBias;

    const int tid = threadIdx.x;
    const int wid = tid >> 5, lane = tid & 31;
    const int wm = wid >> 2;          // 0..1 -> m offset wm*64
    const int wn = wid & 3;           // 0..3 -> n offset wn*32
    const int g = lane >> 2;
    const int t = lane & 3;
    const int bm = blockIdx.y * 128;
    const int bn = blockIdx.x * 128;

    // staging: thread i -> row (i>>2)+l*64 (l=0..1), 16B chunk (i&3)
    const int s_row = tid >> 2;
    const int s_c   = tid & 3;
    const int s_cs  = s_c ^ ((s_row >> 1) & 3);

    // ldmatrix coords
    const int lq = lane >> 3;
    const int lr = lane & 7;
    const int a_frow = wm * 64 + ((lq & 1) << 3) + lr;       // + mt*16
    const int a_ks   = lq >> 1;
    const uint32_t a_sw = (a_frow >> 1) & 3;
    const int b_frow = wn * 32 + ((lq >> 1) << 3) + lr;      // + ntp*16
    const int b_ks   = lq & 1;
    const uint32_t b_sw = (b_frow >> 1) & 3;

    float acc[4][4][4];
#pragma unroll
    for (int mt = 0; mt < 4; mt++)
#pragma unroll
        for (int nt = 0; nt < 4; nt++)
#pragma unroll
            for (int q = 0; q < 4; q++) acc[mt][nt][q] = 0.f;

    const int nch = K >> 5;
    const __half* Agb = A + (size_t)(bm + s_row) * K + s_c * 8;
    const __half* Bgb = B + (size_t)(bn + s_row) * K + s_c * 8;

    // prologue: issue stages 0..2
#pragma unroll
    for (int s = 0; s < NSTAGE - 1; s++) {
        const int k0 = s << 5;
        uint32_t ab = sbase + s * STAGE_BYTES;
#pragma unroll
        for (int l = 0; l < 2; l++)
            cp16(ab + (uint32_t)(((s_row + l * 64) * 4 + s_cs) * 16), Agb + (size_t)l * 64 * K + k0);
        uint32_t bb = ab + 8192;
#pragma unroll
        for (int l = 0; l < 2; l++)
            cp16(bb + (uint32_t)(((s_row + l * 64) * 4 + s_cs) * 16), Bgb + (size_t)l * 64 * K + k0);
        CP_COMMIT();
    }
    CP_WAIT2();
    __syncthreads();

    for (int i = 0; i < nch; i++) {
        const int slot = i & (NSTAGE - 1);
        if (i + NSTAGE - 1 < nch) {
            const int k0 = (i + NSTAGE - 1) << 5;
            uint32_t ab = sbase + ((i + NSTAGE - 1) & (NSTAGE - 1)) * STAGE_BYTES;
#pragma unroll
            for (int l = 0; l < 2; l++)
                cp16(ab + (uint32_t)(((s_row + l * 64) * 4 + s_cs) * 16), Agb + (size_t)l * 64 * K + k0);
            uint32_t bb = ab + 8192;
#pragma unroll
            for (int l = 0; l < 2; l++)
                cp16(bb + (uint32_t)(((s_row + l * 64) * 4 + s_cs) * 16), Bgb + (size_t)l * 64 * K + k0);
        }
        CP_COMMIT();

        const uint32_t abase = sbase + slot * STAGE_BYTES + a_frow * 64;
        const uint32_t bbase = sbase + slot * STAGE_BYTES + 8192 + b_frow * 64;
#pragma unroll
        for (int ks = 0; ks < 2; ks++) {
            const uint32_t a_off = (((uint32_t)(2 * ks + a_ks) ^ a_sw) << 4);
            const uint32_t b_off = (((uint32_t)(2 * ks + b_ks) ^ b_sw) << 4);
            uint32_t af[4][4], bf[4][2];
#pragma unroll
            for (int mt = 0; mt < 4; mt++)
                ldmx4(af[mt][0], af[mt][1], af[mt][2], af[mt][3],
                      abase + mt * 1024 + a_off);
#pragma unroll
            for (int ntp = 0; ntp < 2; ntp++)
                ldmx4(bf[2*ntp][0], bf[2*ntp][1], bf[2*ntp+1][0], bf[2*ntp+1][1],
                      bbase + ntp * 1024 + b_off);
#pragma unroll
            for (int mt = 0; mt < 4; mt++)
#pragma unroll
                for (int nt = 0; nt < 4; nt++)
                    mma_f16(acc[mt][nt], af[mt], bf[nt]);
        }
        CP_WAIT2();
        __syncthreads();
    }

    // ---- epilogue ----
    const int do_gelu = flags & 1, out_half = flags & 2;
#pragma unroll
    for (int mt = 0; mt < 4; mt++) {
        const int row = bm + wm * 64 + mt * 16 + g;
#pragma unroll
        for (int nt = 0; nt < 4; nt++) {
            const int col = bn + wn * 32 + nt * 8 + 2 * t;
            const float bz0 = bias[col], bz1 = bias[col + 1];
            float v[4] = { acc[mt][nt][0] + bz0, acc[mt][nt][1] + bz1,
                           acc[mt][nt][2] + bz0, acc[mt][nt][3] + bz1 };
            if (do_gelu) {
#pragma unroll
                for (int q = 0; q < 4; q++)
                    v[q] = 0.5f * v[q] * (1.0f + erff(v[q] * 0.70710678118654752f));
            }
            if (out_half) {
                __half* C = (__half*)Cb + (size_t)blockIdx.z * sC;
                *(__half2*)(C + (size_t)row * N + col)       = __floats2half2_rn(v[0], v[1]);
                *(__half2*)(C + (size_t)(row + 8) * N + col) = __floats2half2_rn(v[2], v[3]);
            } else {
                float* C = (float*)Cb + (size_t)blockIdx.z * sC;
                *(float2*)(C + (size_t)row * N + col)       = make_float2(v[0], v[1]);
                *(float2*)(C + (size_t)(row + 8) * N + col) = make_float2(v[2], v[3]);
            }
        }
    }
}

// ---------------- weight convert + transpose: [E][K][N] fp32 -> [E][N][K] fp16 -------
__global__ void __launch_bounds__(256) convert_w_kernel(const float* __restrict__ in,
                                                        __half* __restrict__ out,
                                                        int K, int N) {
    __shared__ float tile[32][65];
    const float* w = in + (size_t)blockIdx.z * K * N;
    __half* o = out + (size_t)blockIdx.z * N * K;
    int n0 = blockIdx.x * 32, k0 = blockIdx.y * 64;
    int tx = threadIdx.x & 31, ty = threadIdx.x >> 5;   // 32 x 8
#pragma unroll
    for (int i = 0; i < 8; i++) {
        int k = ty + i * 8;
        tile[tx][k] = w[(size_t)(k0 + k) * N + n0 + tx];
    }
    __syncthreads();
#pragma unroll
    for (int i = 0; i < 4; i++) {
        int n = ty * 4 + i;
        __half2 h = __floats2half2_rn(tile[n][2 * tx], tile[n][2 * tx + 1]);
        *(__half2*)(o + (size_t)(n0 + n) * K + k0 + 2 * tx) = h;
    }
}

// ---------------- router: logits -> softmax -> top2 ----------------
__global__ void __launch_bounds__(256) router_kernel(const float* __restrict__ x,
                                                     const float* __restrict__ wr,
                                                     const float* __restrict__ br) {
    __shared__ float swT[NEXP][DMODEL];
    int tid = threadIdx.x;
    for (int i = tid; i < DMODEL * NEXP; i += 256) {
        int d = i >> 3, e = i & 7;
        swT[e][d] = wr[i];
    }
    __syncthreads();
    int warp = tid >> 5, lane = tid & 31;
    int token = blockIdx.x * 8 + warp;
    const float* xr = x + (size_t)token * DMODEL;
    float p[NEXP];
#pragma unroll
    for (int e = 0; e < NEXP; e++) p[e] = 0.f;
    for (int j = lane; j < DMODEL; j += 32) {
        float xv = xr[j];
#pragma unroll
        for (int e = 0; e < NEXP; e++) p[e] = fmaf(xv, swT[e][j], p[e]);
    }
#pragma unroll
    for (int e = 0; e < NEXP; e++) {
#pragma unroll
        for (int off = 16; off; off >>= 1)
            p[e] += __shfl_xor_sync(0xffffffffu, p[e], off);
    }
    if (lane == 0) {
        float mx = -1e30f;
#pragma unroll
        for (int e = 0; e < NEXP; e++) { p[e] += br[e]; mx = fmaxf(mx, p[e]); }
        float s = 0.f;
#pragma unroll
        for (int e = 0; e < NEXP; e++) { p[e] = expf(p[e] - mx); s += p[e]; }
        float inv = 1.f / s;
#pragma unroll
        for (int e = 0; e < NEXP; e++) p[e] *= inv;
        int b0 = 0; float v0 = p[0];
#pragma unroll
        for (int e = 1; e < NEXP; e++) if (p[e] > v0) { v0 = p[e]; b0 = e; }
        int b1 = -1; float v1 = -1.f;
#pragma unroll
        for (int e = 0; e < NEXP; e++) if (e != b0 && p[e] > v1) { v1 = p[e]; b1 = e; }
        g_topi[token*2]   = b0;  g_topv[token*2]   = v0;
        g_topi[token*2+1] = b1;  g_topv[token*2+1] = v1;
    }
}

// ---------------- arrival-order capacity scan (conflict-free, register-packed) -------
__global__ void __launch_bounds__(1024) scan_kernel() {
    __shared__ int scnt[NEXP][1024];
    const int tid = threadIdx.x, wid = tid >> 5, lane = tid & 31;

    int4 vv[8];
#pragma unroll
    for (int q = 0; q < 8; q++) vv[q] = ((const int4*)g_topi)[tid * 8 + q];

    uint64_t hc = 0;
#pragma unroll
    for (int q = 0; q < 8; q++) {
        hc += 1ULL << (vv[q].x * 8);
        hc += 1ULL << (vv[q].y * 8);
        hc += 1ULL << (vv[q].z * 8);
        hc += 1ULL << (vv[q].w * 8);
    }
#pragma unroll
    for (int e = 0; e < NEXP; e++)
        scnt[e][tid] = (int)((hc >> (e * 8)) & 0xff);
    __syncthreads();

    if (wid < NEXP) {
        const int e = wid;
        int run = 0;
#pragma unroll 4
        for (int r = 0; r < 32; r++) {
            int v = scnt[e][r * 32 + lane];
            int x = v;
#pragma unroll
            for (int off = 1; off < 32; off <<= 1) {
                int y = __shfl_up_sync(0xffffffffu, x, off);
                if (lane >= off) x += y;
            }
            scnt[e][r * 32 + lane] = run + x - v;
            run += __shfl_sync(0xffffffffu, x, 31);
        }
        if (lane == 0) g_kept[e] = run < CAP ? run : CAP;
    }
    __syncthreads();

    uint64_t b0 = 0, b1 = 0;
#pragma unroll
    for (int e = 0; e < 4; e++) b0 |= (uint64_t)(uint32_t)scnt[e][tid] << (e * 16);
#pragma unroll
    for (int e = 4; e < 8; e++) b1 |= (uint64_t)(uint32_t)scnt[e][tid] << ((e - 4) * 16);

    const int a0 = tid * 32;
#pragma unroll
    for (int q = 0; q < 8; q++) {
        int ids[4] = { vv[q].x, vv[q].y, vv[q].z, vv[q].w };
#pragma unroll
        for (int j = 0; j < 4; j++) {
            const int e = ids[j];
            const int a = a0 + q * 4 + j;
            const int sh = (e & 3) * 16;
            uint64_t w = (e < 4) ? b0 : b1;
            const int pos = (int)((w >> sh) & 0xffff);
            w += 1ULL << sh;
            if (e < 4) b0 = w; else b1 = w;
            if (pos < CAP) { g_apos[a] = pos; g_slot_a[e * CAP + pos] = a; }
            else           { g_apos[a] = -1; }
        }
    }
}

// ---------------- dispatch gather (fp32 -> fp16 activations) ----------------
__global__ void __launch_bounds__(256) dispatch_kernel(const float* __restrict__ x) {
    int r = blockIdx.x;
    int e = r / CAP, pos = r - e * CAP;
    uint2* dst = (uint2*)(g_buf + (size_t)r * DMODEL);
    if (pos < g_kept[e]) {
        int a = g_slot_a[r];
        float4 v = ((const float4*)(x + (size_t)(a >> 1) * DMODEL))[threadIdx.x];
        __half2 h0 = __floats2half2_rn(v.x, v.y);
        __half2 h1 = __floats2half2_rn(v.z, v.w);
        uint2 u;
        u.x = *reinterpret_cast<uint32_t*>(&h0);
        u.y = *reinterpret_cast<uint32_t*>(&h1);
        dst[threadIdx.x] = u;
    } else {
        dst[threadIdx.x] = make_uint2(0u, 0u);
    }
}

// ---------------- combine ----------------
__global__ void __launch_bounds__(256) combine_kernel(float* __restrict__ out) {
    int token = blockIdx.x;
    int a0 = token * 2;
    int p0 = g_apos[a0], p1 = g_apos[a0 + 1];
    float w0 = (p0 >= 0) ? g_topv[a0]     : 0.f;
    float w1 = (p1 >= 0) ? g_topv[a0 + 1] : 0.f;
    float ws = w0 + w1;
    int t4 = threadIdx.x;
    float4 acc = make_float4(0.f, 0.f, 0.f, 0.f);
    if (p0 >= 0) {
        const float4* r = (const float4*)(g_y + ((size_t)g_topi[a0] * CAP + p0) * DMODEL);
        float4 v = r[t4];
        acc.x = fmaf(w0, v.x, acc.x); acc.y = fmaf(w0, v.y, acc.y);
        acc.z = fmaf(w0, v.z, acc.z); acc.w = fmaf(w0, v.w, acc.w);
    }
    if (p1 >= 0) {
        const float4* r = (const float4*)(g_y + ((size_t)g_topi[a0 + 1] * CAP + p1) * DMODEL);
        float4 v = r[t4];
        acc.x = fmaf(w1, v.x, acc.x); acc.y = fmaf(w1, v.y, acc.y);
        acc.z = fmaf(w1, v.z, acc.z); acc.w = fmaf(w1, v.w, acc.w);
    }
    if (ws > 0.f) {
        float inv = 1.f / fmaxf(ws, 1e-6f);
        acc.x *= inv; acc.y *= inv; acc.z *= inv; acc.w *= inv;
    }
    ((float4*)(out + (size_t)token * DMODEL))[t4] = acc;
}

// ---------------- launch ----------------
#define SMEM_TOTAL (NSTAGE * STAGE_BYTES)   // 64 KB per CTA

extern "C" void kernel_launch(void* const* d_in, const int* in_sizes, int n_in,
                              void* d_out, int out_size) {
    const float* x  = (const float*)d_in[0];
    const float* wr = (const float*)d_in[1];
    const float* br = (const float*)d_in[2];
    const float* w1 = (const float*)d_in[3];
    const float* b1 = (const float*)d_in[4];
    const float* w2 = (const float*)d_in[5];
    const float* b2 = (const float*)d_in[6];
    float* y = (float*)d_out;

    __half *buf, *h, *w1h, *w2h;
    float *yy;
    cudaGetSymbolAddress((void**)&buf, g_buf);
    cudaGetSymbolAddress((void**)&h,   g_h);
    cudaGetSymbolAddress((void**)&yy,  g_y);
    cudaGetSymbolAddress((void**)&w1h, g_w1h);
    cudaGetSymbolAddress((void**)&w2h, g_w2h);

    cudaFuncSetAttribute(moe_mma_kernel, cudaFuncAttributeMaxDynamicSharedMemorySize, SMEM_TOTAL);

    // weights: fp32 [K][N] -> fp16 [N][K]
    convert_w_kernel<<<dim3(FF / 32, DMODEL / 64, NEXP), 256>>>(w1, w1h, DMODEL, FF);
    convert_w_kernel<<<dim3(DMODEL / 32, FF / 64, NEXP), 256>>>(w2, w2h, FF, DMODEL);

    router_kernel<<<NTOK / 8, 256>>>(x, wr, br);
    scan_kernel<<<1, 1024>>>();
    dispatch_kernel<<<NEXP * CAP, 256>>>(x);

    // GEMM1: h = fp16(GELU(buf @ w1 + b1))   [per expert: 2560x1024 @ 1024x4096]
    dim3 g1(FF / 128, CAP / 128, NEXP);       // 32 x 20 x 8
    moe_mma_kernel<<<g1, 256, SMEM_TOTAL>>>(buf, w1h, b1, (void*)h, FF, DMODEL, 3,
                              (long)CAP * DMODEL, (long)DMODEL * FF, FF, (long)CAP * FF);

    // GEMM2: y_e = h @ w2 + b2 (fp32 out)    [per expert: 2560x4096 @ 4096x1024]
    dim3 g2(DMODEL / 128, CAP / 128, NEXP);   // 8 x 20 x 8
    moe_mma_kernel<<<g2, 256, SMEM_TOTAL>>>(h, w2h, b2, (void*)yy, DMODEL, FF, 0,
                              (long)CAP * FF, (long)FF * DMODEL, DMODEL, (long)CAP * DMODEL);

    combine_kernel<<<NTOK, 256>>>(y);
}